// round 2
// baseline (speedup 1.0000x reference)
#include <cuda_runtime.h>

// Problem constants (fixed by the reference)
#define NN   50000
#define NPAD 50048          // multiple of 64 for GEMM tiling
#define NE   400000
#define HID  128
#define NLAY 3
#define NH   4
#define NG   512

// ---------------- scratch (device globals; no allocation allowed) ----------------
__device__ float g_h  [NPAD*HID];
__device__ float g_hn [NPAD*HID];
__device__ float g_q  [NPAD*HID];
__device__ float g_k  [NPAD*HID];
__device__ float g_v  [NPAD*HID];
__device__ float g_xr [NPAD*HID];
__device__ float g_out[NPAD*HID];   // zero-initialized; pad rows never written
__device__ float g_f1 [NPAD*HID];
__device__ float g_f2 [NPAD*HID];
__device__ float g_efeat[NE*10];
__device__ float g_logits[NE*NH];
__device__ int   g_deg[NN];
__device__ int   g_rowptr[NN+1];
__device__ int   g_cursor[NN];
__device__ int   g_csr[NE];
__device__ float g_pooled[NG*HID];

__device__ __forceinline__ float sp_f(float x){ return x > 20.f ? x : log1pf(expf(x)); }

// ---------------- init / zero ----------------
__global__ void k_init(const float* __restrict__ h){
    int i = blockIdx.x*256 + threadIdx.x;
    if(i < NPAD*HID) g_h[i] = (i < NN*HID) ? h[i] : 0.f;
}
__global__ void k_zero_all(){
    int i = blockIdx.x*256 + threadIdx.x;
    if(i < NN){ g_deg[i] = 0; g_cursor[i] = 0; }
    if(i < NG*HID) g_pooled[i] = 0.f;
}

// ---------------- edge features (RBF) ----------------
__global__ void k_efeat(const float* __restrict__ pos, const float* __restrict__ ew,
                        const int* __restrict__ ei){
    int e = blockIdx.x*256 + threadIdx.x;
    if(e >= NE) return;
    int s = ei[e], d = ei[NE+e];
    float dx = pos[d*3+0]-pos[s*3+0];
    float dy = pos[d*3+1]-pos[s*3+1];
    float dz = pos[d*3+2]-pos[s*3+2];
    float D  = sqrtf(dx*dx+dy*dy+dz*dz);
    float x  = D*0.1f;
    float cut = 0.f;
    if(x < 1.f){
        float x3=x*x*x, x4=x3*x, x5=x4*x;
        cut = 1.f - 6.f*x5 + 15.f*x4 - 10.f*x3;
    }
    float ed = expf(-D);
    const float cK = expf(-10.f);
    const float dc = (cK - 1.f)/8.f;
    float w = 4.5f/(1.f - cK); w = w*w;   // width
    #pragma unroll
    for(int r=0;r<9;r++){
        float c = 1.f + (float)r*dc;
        float t = ed - c;
        g_efeat[e*10+r] = cut * expf(-w*t*t);
    }
    g_efeat[e*10+9] = ew[e];
}

// ---------------- CSR build (by dst) ----------------
__global__ void k_hist(const int* __restrict__ ei){
    int e = blockIdx.x*256 + threadIdx.x;
    if(e < NE) atomicAdd(&g_deg[ei[NE+e]], 1);
}
__global__ void k_scan(){   // single block, 1024 threads: exclusive scan of g_deg
    __shared__ int sd[1024];
    __shared__ int carry;
    int tid = threadIdx.x;
    if(tid==0) carry = 0;
    __syncthreads();
    for(int base=0; base<NN; base+=1024){
        int i = base + tid;
        int v = (i < NN) ? g_deg[i] : 0;
        sd[tid] = v; __syncthreads();
        #pragma unroll
        for(int off=1; off<1024; off<<=1){
            int t = (tid >= off) ? sd[tid-off] : 0;
            __syncthreads();
            sd[tid] += t;
            __syncthreads();
        }
        if(i < NN) g_rowptr[i] = carry + sd[tid] - v;
        int total = sd[1023];
        __syncthreads();
        if(tid==0) carry += total;
        __syncthreads();
    }
    if(tid==0) g_rowptr[NN] = carry;
}
__global__ void k_scatter(const int* __restrict__ ei){
    int e = blockIdx.x*256 + threadIdx.x;
    if(e >= NE) return;
    int d = ei[NE+e];
    int p = atomicAdd(&g_cursor[d], 1);
    g_csr[g_rowptr[d] + p] = e;
}

// ---------------- LayerNorm (warp per node) ----------------
__global__ void k_ln(const float* __restrict__ gam, const float* __restrict__ bet){
    int n = blockIdx.x*4 + (threadIdx.x>>5);
    if(n >= NPAD) return;
    int lane = threadIdx.x & 31;
    float4 x = ((const float4*)g_h)[n*32 + lane];
    float s  = x.x+x.y+x.z+x.w;
    float ss = x.x*x.x+x.y*x.y+x.z*x.z+x.w*x.w;
    #pragma unroll
    for(int o=16;o;o>>=1){
        s  += __shfl_xor_sync(0xffffffffu, s,  o);
        ss += __shfl_xor_sync(0xffffffffu, ss, o);
    }
    float mean = s*(1.f/128.f);
    float var  = ss*(1.f/128.f) - mean*mean;
    float inv  = rsqrtf(var + 1e-5f);
    float4 g4 = ((const float4*)gam)[lane];
    float4 b4 = ((const float4*)bet)[lane];
    float4 y;
    y.x=(x.x-mean)*inv*g4.x+b4.x;
    y.y=(x.y-mean)*inv*g4.y+b4.y;
    y.z=(x.z-mean)*inv*g4.z+b4.z;
    y.w=(x.w-mean)*inv*g4.w+b4.w;
    ((float4*)g_hn)[n*32 + lane] = y;
}

// ---------------- GEMM: out[NPAD,128] = A[NPAD,128] @ W[128,128] + b  (opt act/residual) ----------------
// block 256 (8 warps), warp computes 8 rows x 128 cols; lane owns 4 contiguous cols.
template<int ACT, int RES>
__global__ void k_gemm(const float* __restrict__ A, const float* __restrict__ W,
                       const float* __restrict__ bias, const float* __restrict__ res,
                       float* __restrict__ out){
    int warp = threadIdx.x>>5, lane = threadIdx.x&31;
    int row0 = blockIdx.x*64 + warp*8;
    const float4* A4 = (const float4*)(A + (size_t)row0*HID);
    const float4* W4 = (const float4*)W;
    float4 b4 = ((const float4*)bias)[lane];
    float4 acc[8];
    #pragma unroll
    for(int r=0;r<8;r++) acc[r]=b4;
    #pragma unroll 2
    for(int k=0;k<HID;k+=4){
        float4 w0=W4[(k+0)*32+lane], w1=W4[(k+1)*32+lane];
        float4 w2=W4[(k+2)*32+lane], w3=W4[(k+3)*32+lane];
        #pragma unroll
        for(int r=0;r<8;r++){
            float4 a = A4[r*32 + (k>>2)];
            acc[r].x += a.x*w0.x + a.y*w1.x + a.z*w2.x + a.w*w3.x;
            acc[r].y += a.x*w0.y + a.y*w1.y + a.z*w2.y + a.w*w3.y;
            acc[r].z += a.x*w0.z + a.y*w1.z + a.z*w2.z + a.w*w3.z;
            acc[r].w += a.x*w0.w + a.y*w1.w + a.z*w2.w + a.w*w3.w;
        }
    }
    #pragma unroll
    for(int r=0;r<8;r++){
        float4 v = acc[r];
        if(ACT==1){ v.x=sp_f(v.x); v.y=sp_f(v.y); v.z=sp_f(v.z); v.w=sp_f(v.w); }
        if(RES){
            float4 rr = ((const float4*)(res + (size_t)(row0+r)*HID))[lane];
            v.x+=rr.x; v.y+=rr.y; v.z+=rr.z; v.w+=rr.w;
        }
        ((float4*)(out + (size_t)(row0+r)*HID))[lane] = v;
    }
}

// ---------------- attention logits (warp per edge) ----------------
__global__ void k_logits(const int* __restrict__ ei, const float* __restrict__ We){
    int e = blockIdx.x*4 + (threadIdx.x>>5);
    if(e >= NE) return;
    int lane = threadIdx.x & 31;
    int s = ei[e], d = ei[NE+e];
    float4 q4 = ((const float4*)g_q)[d*32 + lane];
    float4 k4 = ((const float4*)g_k)[s*32 + lane];
    float4 ea = make_float4(0.f,0.f,0.f,0.f);
    #pragma unroll
    for(int r=0;r<10;r++){
        float ef = g_efeat[e*10+r];
        float4 w = ((const float4*)We)[r*32 + lane];
        ea.x += ef*w.x; ea.y += ef*w.y; ea.z += ef*w.z; ea.w += ef*w.w;
    }
    float p = q4.x*(k4.x+ea.x) + q4.y*(k4.y+ea.y) + q4.z*(k4.z+ea.z) + q4.w*(k4.w+ea.w);
    p += __shfl_xor_sync(0xffffffffu, p, 1);
    p += __shfl_xor_sync(0xffffffffu, p, 2);
    p += __shfl_xor_sync(0xffffffffu, p, 4);
    if((lane&7)==0) g_logits[e*4 + (lane>>3)] = p * 0.17677669529663687f; // 1/sqrt(32)
}

// ---------------- softmax + message aggregation (warp per node, no float atomics) ----------------
__global__ void k_agg(const int* __restrict__ ei, const float* __restrict__ We){
    int n = blockIdx.x*4 + (threadIdx.x>>5);
    if(n >= NN) return;
    int lane = threadIdx.x & 31, head = lane>>3;
    int row = g_rowptr[n];
    int deg = g_rowptr[n+1] - row;
    float m = -1e30f;
    for(int i=0;i<deg;i++) m = fmaxf(m, g_logits[g_csr[row+i]*4 + head]);
    float4 acc = make_float4(0.f,0.f,0.f,0.f);
    float ssum = 0.f;
    for(int i=0;i<deg;i++){
        int e = g_csr[row+i];
        int s = ei[e];
        float w = expf(g_logits[e*4 + head] - m);
        ssum += w;
        float4 v4 = ((const float4*)g_v)[s*32 + lane];
        float4 ea = make_float4(0.f,0.f,0.f,0.f);
        #pragma unroll
        for(int r=0;r<10;r++){
            float ef = g_efeat[e*10+r];
            float4 ww = ((const float4*)We)[r*32 + lane];
            ea.x += ef*ww.x; ea.y += ef*ww.y; ea.z += ef*ww.z; ea.w += ef*ww.w;
        }
        acc.x += w*(v4.x+ea.x); acc.y += w*(v4.y+ea.y);
        acc.z += w*(v4.z+ea.z); acc.w += w*(v4.w+ea.w);
    }
    float inv = (deg>0) ? 1.f/ssum : 0.f;
    float4 o; o.x=acc.x*inv; o.y=acc.y*inv; o.z=acc.z*inv; o.w=acc.w*inv;
    ((float4*)g_out)[n*32 + lane] = o;
}

// ---------------- gated skip + softplus residual ----------------
__global__ void k_combine(const float* __restrict__ Wb){
    int n = blockIdx.x*4 + (threadIdx.x>>5);
    if(n >= NPAD) return;
    int lane = threadIdx.x & 31;
    float4 o  = ((const float4*)g_out)[n*32+lane];
    float4 x  = ((const float4*)g_xr )[n*32+lane];
    float4 hn = ((const float4*)g_hn )[n*32+lane];
    float4 w0 = ((const float4*)Wb)[lane];
    float4 w1 = ((const float4*)Wb)[32+lane];
    float4 w2 = ((const float4*)Wb)[64+lane];
    float p = o.x*w0.x + o.y*w0.y + o.z*w0.z + o.w*w0.w
            + x.x*w1.x + x.y*w1.y + x.z*w1.z + x.w*w1.w
            + (o.x-x.x)*w2.x + (o.y-x.y)*w2.y + (o.z-x.z)*w2.z + (o.w-x.w)*w2.w;
    #pragma unroll
    for(int off=16;off;off>>=1) p += __shfl_xor_sync(0xffffffffu, p, off);
    float beta = 1.f/(1.f+expf(-p));
    float4 r;
    r.x = beta*x.x + (1.f-beta)*o.x;
    r.y = beta*x.y + (1.f-beta)*o.y;
    r.z = beta*x.z + (1.f-beta)*o.z;
    r.w = beta*x.w + (1.f-beta)*o.w;
    float4 hout;
    hout.x = hn.x + sp_f(r.x); hout.y = hn.y + sp_f(r.y);
    hout.z = hn.z + sp_f(r.z); hout.w = hn.w + sp_f(r.w);
    ((float4*)g_h)[n*32+lane] = hout;
}

// ---------------- graph pooling + readout head ----------------
__global__ void k_pool(const int* __restrict__ batch){
    int n = blockIdx.x*4 + (threadIdx.x>>5);
    if(n >= NN) return;
    int lane = threadIdx.x & 31;
    int g = batch[n];
    float4 v = ((const float4*)g_h)[n*32+lane];
    float* base = &g_pooled[g*HID + 4*lane];
    atomicAdd(base+0, v.x); atomicAdd(base+1, v.y);
    atomicAdd(base+2, v.z); atomicAdd(base+3, v.w);
}
__global__ void k_final(const float* __restrict__ Wo1, const float* __restrict__ bo1,
                        const float* __restrict__ Wo2, const float* __restrict__ bo2,
                        float* __restrict__ out){
    int g = blockIdx.x*4 + (threadIdx.x>>5);
    if(g >= NG) return;
    int lane = threadIdx.x & 31;
    float4 acc = ((const float4*)bo1)[lane];
    const float* p = &g_pooled[g*HID];
    for(int k2=0;k2<HID;k2++){
        float a = p[k2];
        float4 w = ((const float4*)Wo1)[k2*32 + lane];
        acc.x += a*w.x; acc.y += a*w.y; acc.z += a*w.z; acc.w += a*w.w;
    }
    float4 w2 = ((const float4*)Wo2)[lane];
    float r = sp_f(acc.x)*w2.x + sp_f(acc.y)*w2.y + sp_f(acc.z)*w2.z + sp_f(acc.w)*w2.w;
    #pragma unroll
    for(int off=16;off;off>>=1) r += __shfl_xor_sync(0xffffffffu, r, off);
    if(lane==0) out[g] = r + bo2[0];
}

// ---------------- driver ----------------
extern "C" void kernel_launch(void* const* d_in, const int* in_sizes, int n_in,
                              void* d_out, int out_size){
    const float* h   = (const float*)d_in[0];
    const float* pos = (const float*)d_in[1];
    const float* ew  = (const float*)d_in[2];
    const float* Wq  = (const float*)d_in[3];  const float* bq = (const float*)d_in[4];
    const float* Wk  = (const float*)d_in[5];  const float* bk = (const float*)d_in[6];
    const float* Wv  = (const float*)d_in[7];  const float* bv = (const float*)d_in[8];
    const float* We  = (const float*)d_in[9];
    const float* Ws  = (const float*)d_in[10]; const float* bs = (const float*)d_in[11];
    const float* Wb  = (const float*)d_in[12];
    const float* W1  = (const float*)d_in[13]; const float* b1 = (const float*)d_in[14];
    const float* W2  = (const float*)d_in[15]; const float* b2 = (const float*)d_in[16];
    const float* W3  = (const float*)d_in[17]; const float* b3 = (const float*)d_in[18];
    const float* lgm = (const float*)d_in[19]; const float* lbt = (const float*)d_in[20];
    const float* Wo1 = (const float*)d_in[21]; const float* bo1 = (const float*)d_in[22];
    const float* Wo2 = (const float*)d_in[23]; const float* bo2 = (const float*)d_in[24];
    const int*   ei  = (const int*)d_in[25];
    const int*   bat = (const int*)d_in[26];
    float* out = (float*)d_out;

    float *p_h,*p_hn,*p_q,*p_k,*p_v,*p_xr,*p_f1,*p_f2;
    cudaGetSymbolAddress((void**)&p_h,  g_h);
    cudaGetSymbolAddress((void**)&p_hn, g_hn);
    cudaGetSymbolAddress((void**)&p_q,  g_q);
    cudaGetSymbolAddress((void**)&p_k,  g_k);
    cudaGetSymbolAddress((void**)&p_v,  g_v);
    cudaGetSymbolAddress((void**)&p_xr, g_xr);
    cudaGetSymbolAddress((void**)&p_f1, g_f1);
    cudaGetSymbolAddress((void**)&p_f2, g_f2);

    k_init   <<<(NPAD*HID+255)/256, 256>>>(h);
    k_zero_all<<<(NG*HID+255)/256, 256>>>();
    k_efeat  <<<(NE+255)/256, 256>>>(pos, ew, ei);
    k_hist   <<<(NE+255)/256, 256>>>(ei);
    k_scan   <<<1, 1024>>>();
    k_scatter<<<(NE+255)/256, 256>>>(ei);

    for(int i=0;i<NLAY;i++){
        const float* Wqi=Wq+i*HID*HID; const float* bqi=bq+i*HID;
        const float* Wki=Wk+i*HID*HID; const float* bki=bk+i*HID;
        const float* Wvi=Wv+i*HID*HID; const float* bvi=bv+i*HID;
        const float* Wsi=Ws+i*HID*HID; const float* bsi=bs+i*HID;
        const float* Wei=We+i*10*HID;
        const float* Wbi=Wb+i*3*HID;
        const float* W1i=W1+i*HID*HID; const float* b1i=b1+i*HID;
        const float* W2i=W2+i*HID*HID; const float* b2i=b2+i*HID;
        const float* W3i=W3+i*HID*HID; const float* b3i=b3+i*HID;

        k_ln<<<NPAD/4, 128>>>(lgm, lbt);
        k_gemm<0,0><<<NPAD/64, 256>>>(p_hn, Wqi, bqi, nullptr, p_q);
        k_gemm<0,0><<<NPAD/64, 256>>>(p_hn, Wki, bki, nullptr, p_k);
        k_gemm<0,0><<<NPAD/64, 256>>>(p_hn, Wvi, bvi, nullptr, p_v);
        k_gemm<0,0><<<NPAD/64, 256>>>(p_hn, Wsi, bsi, nullptr, p_xr);
        k_logits<<<NE/4, 128>>>(ei, Wei);
        k_agg<<<(NN+3)/4, 128>>>(ei, Wei);
        k_combine<<<NPAD/4, 128>>>(Wbi);
        k_ln<<<NPAD/4, 128>>>(lgm, lbt);
        k_gemm<1,0><<<NPAD/64, 256>>>(p_hn, W1i, b1i, nullptr, p_f1);
        k_gemm<1,0><<<NPAD/64, 256>>>(p_f1, W2i, b2i, nullptr, p_f2);
        k_gemm<1,1><<<NPAD/64, 256>>>(p_f2, W3i, b3i, p_hn, p_h);
    }

    k_pool <<<(NN+3)/4, 128>>>(bat);
    k_final<<<NG/4, 128>>>(Wo1, bo1, Wo2, bo2, out);
}